// round 5
// baseline (speedup 1.0000x reference)
#include <cuda_runtime.h>
#include <cstdint>

#define D_IN   4096
#define D_OUT  4096
#define NROWS  8192
#define RANK   16

// -------- scratch (static __device__ allowed; no cudaMalloc) --------
__device__ __align__(16) float g_W[D_IN * D_OUT];   // dequantized, tf32-rounded
__device__ __align__(16) float g_T[NROWS * RANK];   // X @ L1

// -------- helpers --------
__device__ __forceinline__ uint32_t f2tf32(float f) {
    uint32_t r;
    asm("cvt.rna.tf32.f32 %0, %1;" : "=r"(r) : "f"(f));
    return r;
}

__device__ __forceinline__ uint32_t smem_u32(const void* p) {
    return (uint32_t)__cvta_generic_to_shared(p);
}

#define CP_ASYNC16(dst, src) \
    asm volatile("cp.async.cg.shared.global [%0], [%1], 16;\n" :: "r"(dst), "l"(src))
#define CP_COMMIT asm volatile("cp.async.commit_group;\n" ::: "memory")
#define CP_WAIT(n) asm volatile("cp.async.wait_group %0;\n" :: "n"(n) : "memory")

__device__ __forceinline__ void mma_m16n8k8_tf32(float* c, const uint32_t* a, const uint32_t* b) {
    asm volatile(
        "mma.sync.aligned.m16n8k8.row.col.f32.tf32.tf32.f32 "
        "{%0,%1,%2,%3}, {%4,%5,%6,%7}, {%8,%9}, {%0,%1,%2,%3};\n"
        : "+f"(c[0]), "+f"(c[1]), "+f"(c[2]), "+f"(c[3])
        : "r"(a[0]), "r"(a[1]), "r"(a[2]), "r"(a[3]), "r"(b[0]), "r"(b[1]));
}

// ============================================================
// Kernel 1: dequant  W = (W_nf4 * c1) * c_kbit2, rounded to tf32
// ============================================================
__global__ void dequant_kernel(const float* __restrict__ w,
                               const float* __restrict__ c1p,
                               const float* __restrict__ ck) {
    const float c1 = c1p[0];
    const int i = (blockIdx.x * blockDim.x + threadIdx.x) * 4;
    float4 a = *(const float4*)(w + i);
    float4 b = *(const float4*)(ck + i);
    float4 o;
    o.x = __uint_as_float(f2tf32((a.x * c1) * b.x));
    o.y = __uint_as_float(f2tf32((a.y * c1) * b.y));
    o.z = __uint_as_float(f2tf32((a.z * c1) * b.z));
    o.w = __uint_as_float(f2tf32((a.w * c1) * b.w));
    *(float4*)(g_W + i) = o;
}

// ============================================================
// Kernel 2: T = X @ L1   (2 rows per block, 128 threads)
// ============================================================
__global__ void xl1_kernel(const float* __restrict__ X, const float* __restrict__ L1) {
    const int row0 = blockIdx.x * 2;
    const int tid  = threadIdx.x;
    const float4* x0 = (const float4*)(X + (size_t)row0 * D_IN);
    const float4* x1 = (const float4*)(X + (size_t)(row0 + 1) * D_IN);

    float acc0[RANK], acc1[RANK];
    #pragma unroll
    for (int r = 0; r < RANK; r++) { acc0[r] = 0.f; acc1[r] = 0.f; }

    for (int k4 = tid; k4 < D_IN / 4; k4 += 128) {
        float4 xa = x0[k4];
        float4 xb = x1[k4];
        const float* l = L1 + k4 * 4 * RANK;   // L1[k][r] row-major
        #pragma unroll
        for (int r = 0; r < RANK; r++) {
            float l0 = l[r], l1 = l[RANK + r], l2 = l[2 * RANK + r], l3 = l[3 * RANK + r];
            acc0[r] += xa.x * l0 + xa.y * l1 + xa.z * l2 + xa.w * l3;
            acc1[r] += xb.x * l0 + xb.y * l1 + xb.z * l2 + xb.w * l3;
        }
    }
    // warp reduce
    #pragma unroll
    for (int off = 16; off > 0; off >>= 1) {
        #pragma unroll
        for (int r = 0; r < RANK; r++) {
            acc0[r] += __shfl_xor_sync(0xFFFFFFFF, acc0[r], off);
            acc1[r] += __shfl_xor_sync(0xFFFFFFFF, acc1[r], off);
        }
    }
    __shared__ float red[4][32];
    const int warp = tid >> 5, lane = tid & 31;
    if (lane == 0) {
        #pragma unroll
        for (int r = 0; r < RANK; r++) {
            red[warp][r]        = acc0[r];
            red[warp][RANK + r] = acc1[r];
        }
    }
    __syncthreads();
    if (tid < 32) {
        float s = red[0][tid] + red[1][tid] + red[2][tid] + red[3][tid];
        int r = tid & 15, which = tid >> 4;
        g_T[(size_t)(row0 + which) * RANK + r] = s;
    }
}

// ============================================================
// Kernel 3: Y = X @ g_W  (tf32 mma.sync, BM=128 BN=128 BK=16)
// ============================================================
#define BM 128
#define BN 128
#define BK 16
#define AS_STRIDE 20    // conflict-free for A fragment pattern (20g mod 32 distinct)
#define BS_STRIDE 136   // conflict-free for B fragment pattern (8*t4 octets)

__global__ __launch_bounds__(256)
void gemm_tf32_kernel(const float* __restrict__ X, float* __restrict__ Y) {
    __shared__ __align__(16) float As[2][BM * AS_STRIDE];
    __shared__ __align__(16) float Bs[2][BK * BS_STRIDE];

    const int tid  = threadIdx.x;
    const int bM   = blockIdx.y, bN = blockIdx.x;
    const int warp = tid >> 5,   lane = tid & 31;
    const int wm   = warp & 3,   wn   = warp >> 2;   // 4 x 2 warp grid
    const int g    = lane >> 2,  t4   = lane & 3;

    const float* Xg = X   + (size_t)(bM * BM) * D_IN;
    const float* Wg = g_W + (size_t)(bN * BN);

    float c[2][8][4];
    #pragma unroll
    for (int mt = 0; mt < 2; mt++)
        #pragma unroll
        for (int nt = 0; nt < 8; nt++)
            #pragma unroll
            for (int i = 0; i < 4; i++) c[mt][nt][i] = 0.f;

    auto load_tile = [&](int buf, int kt) {
        float* Ad = As[buf];
        float* Bd = Bs[buf];
        #pragma unroll
        for (int i = 0; i < 2; i++) {
            int t = tid * 2 + i;
            // A tasks: 128 rows x 4 float4 of 16 k
            int r = t >> 2, c4 = t & 3;
            CP_ASYNC16(smem_u32(Ad + r * AS_STRIDE + c4 * 4),
                       Xg + (size_t)r * D_IN + kt * BK + c4 * 4);
        }
        #pragma unroll
        for (int i = 0; i < 2; i++) {
            int t = tid * 2 + i;
            // B tasks: 16 k-rows x 32 float4 of 128 n
            int r = t >> 5, c4 = t & 31;
            CP_ASYNC16(smem_u32(Bd + r * BS_STRIDE + c4 * 4),
                       Wg + (size_t)(kt * BK + r) * D_OUT + c4 * 4);
        }
    };

    auto compute = [&](int buf) {
        const float* Ab = As[buf];
        const float* Bb = Bs[buf];
        #pragma unroll
        for (int kk = 0; kk < BK; kk += 8) {
            uint32_t a[2][4];
            #pragma unroll
            for (int mt = 0; mt < 2; mt++) {
                int row = wm * 32 + mt * 16 + g;
                a[mt][0] = f2tf32(Ab[row       * AS_STRIDE + kk + t4]);
                a[mt][1] = f2tf32(Ab[(row + 8) * AS_STRIDE + kk + t4]);
                a[mt][2] = f2tf32(Ab[row       * AS_STRIDE + kk + t4 + 4]);
                a[mt][3] = f2tf32(Ab[(row + 8) * AS_STRIDE + kk + t4 + 4]);
            }
            uint32_t b[8][2];
            #pragma unroll
            for (int nt = 0; nt < 8; nt++) {
                int col = wn * 64 + nt * 8 + g;
                b[nt][0] = __float_as_uint(Bb[(kk + t4)     * BS_STRIDE + col]);
                b[nt][1] = __float_as_uint(Bb[(kk + t4 + 4) * BS_STRIDE + col]);
            }
            #pragma unroll
            for (int mt = 0; mt < 2; mt++)
                #pragma unroll
                for (int nt = 0; nt < 8; nt++)
                    mma_m16n8k8_tf32(c[mt][nt], a[mt], b[nt]);
        }
    };

    load_tile(0, 0);
    CP_COMMIT;
    const int KT = D_IN / BK;   // 256
    for (int kt = 0; kt < KT; ++kt) {
        int cur = kt & 1;
        if (kt + 1 < KT) {
            load_tile(cur ^ 1, kt + 1);
            CP_COMMIT;
            CP_WAIT(1);
        } else {
            CP_WAIT(0);
        }
        __syncthreads();
        compute(cur);
        __syncthreads();   // protect buf `cur` before next iteration reloads it
    }

    float* Yb = Y + (size_t)(bM * BM) * D_OUT + bN * BN;
    #pragma unroll
    for (int mt = 0; mt < 2; mt++) {
        int row = wm * 32 + mt * 16 + g;
        #pragma unroll
        for (int nt = 0; nt < 8; nt++) {
            int col = wn * 64 + nt * 8 + t4 * 2;
            float2 v0 = make_float2(c[mt][nt][0], c[mt][nt][1]);
            float2 v1 = make_float2(c[mt][nt][2], c[mt][nt][3]);
            *(float2*)(Yb + (size_t)row       * D_OUT + col) = v0;
            *(float2*)(Yb + (size_t)(row + 8) * D_OUT + col) = v1;
        }
    }
}

// ============================================================
// Kernel 4: Y += T @ L2   (32 rows x 256 cols per block)
// ============================================================
#define LA_ROWS 32
#define LA_COLS 256

__global__ void lora_add_kernel(const float* __restrict__ L2, float* __restrict__ Y) {
    __shared__ __align__(16) float l2s[RANK][LA_COLS];
    __shared__ __align__(16) float ts[LA_ROWS][RANK];

    const int row0 = blockIdx.y * LA_ROWS;
    const int col0 = blockIdx.x * LA_COLS;
    const int tid  = threadIdx.x;

    for (int i = tid; i < RANK * LA_COLS / 4; i += 256) {
        int r = i / (LA_COLS / 4), cc = i % (LA_COLS / 4);
        *(float4*)&l2s[r][cc * 4] = *(const float4*)(L2 + (size_t)r * D_OUT + col0 + cc * 4);
    }
    if (tid < LA_ROWS * RANK / 4) {
        int r = tid >> 2, cc = tid & 3;
        *(float4*)&ts[r][cc * 4] = *(const float4*)(g_T + (size_t)(row0 + r) * RANK + cc * 4);
    }
    __syncthreads();

    const int r     = tid >> 3;          // 0..31
    const int cbase = (tid & 7) * 4;     // 0..28
    float t[RANK];
    #pragma unroll
    for (int i = 0; i < RANK; i++) t[i] = ts[r][i];

    float* yrow = Y + (size_t)(row0 + r) * D_OUT + col0;
    #pragma unroll
    for (int j = 0; j < 8; j++) {
        int cc = cbase + j * 32;
        float4 y = *(float4*)(yrow + cc);
        #pragma unroll
        for (int i = 0; i < RANK; i++) {
            y.x += t[i] * l2s[i][cc];
            y.y += t[i] * l2s[i][cc + 1];
            y.z += t[i] * l2s[i][cc + 2];
            y.w += t[i] * l2s[i][cc + 3];
        }
        *(float4*)(yrow + cc) = y;
    }
}

// ============================================================
// launch
// ============================================================
extern "C" void kernel_launch(void* const* d_in, const int* in_sizes, int n_in,
                              void* d_out, int out_size) {
    const float* X  = (const float*)d_in[0];
    const float* Wn = (const float*)d_in[1];
    const float* c1 = (const float*)d_in[2];
    const float* ck = (const float*)d_in[3];
    const float* L1 = (const float*)d_in[4];
    const float* L2 = (const float*)d_in[5];
    float* Y = (float*)d_out;

    dequant_kernel<<<(D_IN * D_OUT / 4) / 256, 256>>>(Wn, c1, ck);
    xl1_kernel<<<NROWS / 2, 128>>>(X, L1);
    dim3 grid(D_OUT / BN, NROWS / BM);
    gemm_tf32_kernel<<<grid, 256>>>(X, Y);
    lora_add_kernel<<<dim3(D_OUT / LA_COLS, NROWS / LA_ROWS), 256>>>(L2, Y);
}

// round 7
// speedup vs baseline: 1.8568x; 1.8568x over previous
#include <cuda_runtime.h>
#include <cuda_fp16.h>
#include <cstdint>

#define D_IN   4096
#define D_OUT  4096
#define NROWS  8192
#define RANK   16

// ---------------- scratch ----------------
__device__ __align__(1024) __half g_Wh[D_OUT * D_IN];  // W^T [N][K], fp16
__device__ __align__(1024) __half g_Xh[NROWS * D_IN];  // X, fp16
__device__ __align__(16)   float  g_T [NROWS * RANK];  // X @ L1 (fp32)

// ---------------- helpers ----------------
__device__ __forceinline__ uint32_t smem_u32(const void* p) {
    return (uint32_t)__cvta_generic_to_shared(p);
}
#define CP_ASYNC16(dst, src) \
    asm volatile("cp.async.cg.shared.global [%0], [%1], 16;\n" :: "r"(dst), "l"(src))
#define CP_COMMIT  asm volatile("cp.async.commit_group;\n" ::: "memory")
#define CP_WAIT1   asm volatile("cp.async.wait_group 1;\n" ::: "memory")
#define CP_WAIT0   asm volatile("cp.async.wait_group 0;\n" ::: "memory")

#define LDSM_X4(r0, r1, r2, r3, a) \
    asm volatile("ldmatrix.sync.aligned.m8n8.x4.shared.b16 {%0,%1,%2,%3}, [%4];" \
        : "=r"(r0), "=r"(r1), "=r"(r2), "=r"(r3) : "r"(a))

__device__ __forceinline__ void mma_16816(float* c, const uint32_t* a, const uint32_t* b) {
    asm volatile(
        "mma.sync.aligned.m16n8k16.row.col.f32.f16.f16.f32 "
        "{%0,%1,%2,%3}, {%4,%5,%6,%7}, {%8,%9}, {%0,%1,%2,%3};\n"
        : "+f"(c[0]), "+f"(c[1]), "+f"(c[2]), "+f"(c[3])
        : "r"(a[0]), "r"(a[1]), "r"(a[2]), "r"(a[3]), "r"(b[0]), "r"(b[1]));
}

// ============================================================
// Kernel 1: dequant + transpose to fp16: g_Wh[n][k] = h(W[k][n]*c1*ck[k][n])
// ============================================================
__global__ void dequant_t_kernel(const float* __restrict__ w,
                                 const float* __restrict__ c1p,
                                 const float* __restrict__ ck) {
    __shared__ float tile[32][33];
    const float c1 = c1p[0];
    const int n0 = blockIdx.x * 32, k0 = blockIdx.y * 32;
    const int tx = threadIdx.x, ty = threadIdx.y;   // (32, 8)
    #pragma unroll
    for (int i = 0; i < 4; i++) {
        int k = k0 + ty + i * 8;
        size_t idx = (size_t)k * D_OUT + n0 + tx;
        tile[ty + i * 8][tx] = (w[idx] * c1) * ck[idx];
    }
    __syncthreads();
    #pragma unroll
    for (int i = 0; i < 4; i++) {
        int n = n0 + ty + i * 8;
        g_Wh[(size_t)n * D_IN + k0 + tx] = __float2half_rn(tile[tx][ty + i * 8]);
    }
}

// ============================================================
// Kernel 2: X -> fp16
// ============================================================
__global__ void xconv_kernel(const float* __restrict__ X) {
    const int i = (blockIdx.x * blockDim.x + threadIdx.x) * 4;
    float4 a = *(const float4*)(X + i);
    __half2 h0 = __floats2half2_rn(a.x, a.y);
    __half2 h1 = __floats2half2_rn(a.z, a.w);
    uint2 o = make_uint2(*(uint32_t*)&h0, *(uint32_t*)&h1);
    *(uint2*)(g_Xh + i) = o;
}

// ============================================================
// Kernel 3: T = X @ L1 (fp32, unchanged — verified)
// ============================================================
__global__ void xl1_kernel(const float* __restrict__ X, const float* __restrict__ L1) {
    const int row0 = blockIdx.x * 2;
    const int tid  = threadIdx.x;
    const float4* x0 = (const float4*)(X + (size_t)row0 * D_IN);
    const float4* x1 = (const float4*)(X + (size_t)(row0 + 1) * D_IN);

    float acc0[RANK], acc1[RANK];
    #pragma unroll
    for (int r = 0; r < RANK; r++) { acc0[r] = 0.f; acc1[r] = 0.f; }

    for (int k4 = tid; k4 < D_IN / 4; k4 += 128) {
        float4 xa = x0[k4];
        float4 xb = x1[k4];
        const float* l = L1 + k4 * 4 * RANK;
        #pragma unroll
        for (int r = 0; r < RANK; r++) {
            float l0 = l[r], l1 = l[RANK + r], l2 = l[2 * RANK + r], l3 = l[3 * RANK + r];
            acc0[r] += xa.x * l0 + xa.y * l1 + xa.z * l2 + xa.w * l3;
            acc1[r] += xb.x * l0 + xb.y * l1 + xb.z * l2 + xb.w * l3;
        }
    }
    #pragma unroll
    for (int off = 16; off > 0; off >>= 1) {
        #pragma unroll
        for (int r = 0; r < RANK; r++) {
            acc0[r] += __shfl_xor_sync(0xFFFFFFFF, acc0[r], off);
            acc1[r] += __shfl_xor_sync(0xFFFFFFFF, acc1[r], off);
        }
    }
    __shared__ float red[4][32];
    const int warp = tid >> 5, lane = tid & 31;
    if (lane == 0) {
        #pragma unroll
        for (int r = 0; r < RANK; r++) {
            red[warp][r]        = acc0[r];
            red[warp][RANK + r] = acc1[r];
        }
    }
    __syncthreads();
    if (tid < 32) {
        float s = red[0][tid] + red[1][tid] + red[2][tid] + red[3][tid];
        int r = tid & 15, which = tid >> 4;
        g_T[(size_t)(row0 + which) * RANK + r] = s;
    }
}

// ============================================================
// Kernel 4: fp16 mma.sync GEMM, BM=128 BN=256 BK=64, ldmatrix,
//           3-stage cp.async pipeline, fused LoRA epilogue
// ============================================================
#define BM 128
#define BN 256
#define BK 64                        // halfs; row = 128 B
#define KT (D_IN / BK)               // 64
#define A_BYTES (BM * BK * 2)        // 16384
#define B_BYTES (BN * BK * 2)        // 32768
#define STAGE_BYTES (A_BYTES + B_BYTES)
#define STAGES 3
#define SMEM_L2  (STAGES * STAGE_BYTES)      // 147456
#define SMEM_TS  (SMEM_L2 + RANK * BN * 4)   // +16384
#define SMEM_TOT (SMEM_TS + BM * RANK * 4)   // +8192 = 172032

__global__ __launch_bounds__(256, 1)
void gemm_hmma_kernel(float* __restrict__ Y, const float* __restrict__ L2) {
    extern __shared__ __align__(1024) unsigned char smem[];
    const uint32_t sbase = smem_u32(smem);
    const int tid = threadIdx.x, warp = tid >> 5, lane = tid & 31;
    const int bN = blockIdx.x, bM = blockIdx.y;
    const int wm = warp & 1, wn = warp >> 1;        // 2 x 4 warps, 64x64 tiles
    const int li = lane & 7, sel = lane >> 3;

    const __half* Ag = g_Xh + (size_t)(bM * BM) * D_IN;
    const __half* Bg = g_Wh + (size_t)(bN * BN) * D_IN;

    auto load_stage = [&](int buf, int kt) {
        const uint32_t ab = sbase + buf * STAGE_BYTES;
        const uint32_t bb = ab + A_BYTES;
        #pragma unroll
        for (int j = 0; j < 4; j++) {          // A: 128 rows x 8 chunks
            int id = tid + j * 256, r = id >> 3, c = id & 7;
            CP_ASYNC16(ab + r * 128 + (((c ^ (r & 7))) << 4),
                       Ag + (size_t)r * D_IN + kt * BK + c * 8);
        }
        #pragma unroll
        for (int j = 0; j < 8; j++) {          // B: 256 rows x 8 chunks
            int id = tid + j * 256, r = id >> 3, c = id & 7;
            CP_ASYNC16(bb + r * 128 + (((c ^ (r & 7))) << 4),
                       Bg + (size_t)r * D_IN + kt * BK + c * 8);
        }
        CP_COMMIT;
    };

    // start pipeline before anything else
    load_stage(0, 0);
    load_stage(1, 1);

    // LoRA operand tiles
    float* l2s = (float*)(smem + SMEM_L2);     // [RANK][BN]
    float* ts  = (float*)(smem + SMEM_TS);     // [BM][RANK]
    #pragma unroll
    for (int j = 0; j < 4; j++) {              // 16*256 floats = 1024 float4
        int idx = tid + j * 256, r = idx >> 6, c4 = idx & 63;
        *(float4*)&l2s[r * BN + c4 * 4] =
            *(const float4*)&L2[(size_t)r * D_OUT + bN * BN + c4 * 4];
    }
    #pragma unroll
    for (int j = 0; j < 2; j++) {              // 128*16 floats = 512 float4
        int idx = tid + j * 256, r = idx >> 2, c4 = idx & 3;
        *(float4*)&ts[r * RANK + c4 * 4] =
            *(const float4*)&g_T[(size_t)(bM * BM + r) * RANK + c4 * 4];
    }

    float c[4][8][4];
    #pragma unroll
    for (int mt = 0; mt < 4; mt++)
        #pragma unroll
        for (int nt = 0; nt < 8; nt++)
            #pragma unroll
            for (int i = 0; i < 4; i++) c[mt][nt][i] = 0.f;

    // per-lane ldmatrix row/col pieces
    const int a_selr = sel & 1, a_selc = sel >> 1;   // A: m0,m1 rows, m2,m3 +k8
    const int b_selr = sel >> 1, b_selc = sel & 1;   // B: m0,m1 +k8 alt, m2,m3 rows+8

    for (int kt = 0; kt < KT; ++kt) {
        if (kt + 2 < KT) { CP_WAIT1; } else { CP_WAIT0; }
        __syncthreads();
        if (kt + 2 < KT) load_stage((kt + 2) % STAGES, kt + 2);

        const uint32_t ab = sbase + (kt % STAGES) * STAGE_BYTES;
        const uint32_t bb = ab + A_BYTES;

        #pragma unroll
        for (int ks = 0; ks < 4; ks++) {       // 4 x k16
            const int c0 = ks * 2;
            uint32_t a[4][4], b[8][2];
            #pragma unroll
            for (int mt = 0; mt < 4; mt++) {
                int row = wm * 64 + mt * 16 + li + a_selr * 8;
                int ch  = c0 + a_selc;
                LDSM_X4(a[mt][0], a[mt][1], a[mt][2], a[mt][3],
                        ab + row * 128 + (((ch ^ (row & 7))) << 4));
            }
            #pragma unroll
            for (int p = 0; p < 4; p++) {
                int row = wn * 64 + p * 16 + li + b_selr * 8;
                int ch  = c0 + b_selc;
                LDSM_X4(b[p * 2][0], b[p * 2][1], b[p * 2 + 1][0], b[p * 2 + 1][1],
                        bb + row * 128 + (((ch ^ (row & 7))) << 4));
            }
            #pragma unroll
            for (int mt = 0; mt < 4; mt++)
                #pragma unroll
                for (int nt = 0; nt < 8; nt++)
                    mma_16816(c[mt][nt], a[mt], b[nt]);
        }
        __syncthreads();
    }

    // ---------- epilogue: Y = C + T @ L2 ----------
    const int r0 = lane >> 2, cp = (lane & 3) * 2;
    #pragma unroll
    for (int mt = 0; mt < 4; mt++) {
        const int lrA = wm * 64 + mt * 16 + r0;       // local rows
        const int lrB = lrA + 8;
        float tA[RANK], tB[RANK];
        #pragma unroll
        for (int r = 0; r < RANK; r++) {
            tA[r] = ts[lrA * RANK + r];
            tB[r] = ts[lrB * RANK + r];
        }
        float* yA = Y + (size_t)(bM * BM + lrA) * D_OUT + bN * BN;
        float* yB = Y + (size_t)(bM * BM + lrB) * D_OUT + bN * BN;
        #pragma unroll
        for (int nt = 0; nt < 8; nt++) {
            const int col = wn * 64 + nt * 8 + cp;
            float2 aacc = make_float2(c[mt][nt][0], c[mt][nt][1]);
            float2 bacc = make_float2(c[mt][nt][2], c[mt][nt][3]);
            #pragma unroll
            for (int r = 0; r < RANK; r++) {
                float2 l = *(const float2*)&l2s[r * BN + col];
                aacc.x += tA[r] * l.x; aacc.y += tA[r] * l.y;
                bacc.x += tB[r] * l.x; bacc.y += tB[r] * l.y;
            }
            *(float2*)(yA + col) = aacc;
            *(float2*)(yB + col) = bacc;
        }
    }
}

// ============================================================
// launch
// ============================================================
extern "C" void kernel_launch(void* const* d_in, const int* in_sizes, int n_in,
                              void* d_out, int out_size) {
    const float* X  = (const float*)d_in[0];
    const float* Wn = (const float*)d_in[1];
    const float* c1 = (const float*)d_in[2];
    const float* ck = (const float*)d_in[3];
    const float* L1 = (const float*)d_in[4];
    const float* L2 = (const float*)d_in[5];
    float* Y = (float*)d_out;

    cudaFuncSetAttribute(gemm_hmma_kernel,
                         cudaFuncAttributeMaxDynamicSharedMemorySize, SMEM_TOT);

    dequant_t_kernel<<<dim3(D_OUT / 32, D_IN / 32), dim3(32, 8)>>>(Wn, c1, ck);
    xconv_kernel<<<(NROWS * D_IN / 4) / 256, 256>>>(X);
    xl1_kernel<<<NROWS / 2, 128>>>(X, L1);
    gemm_hmma_kernel<<<dim3(D_OUT / BN, NROWS / BM), 256, SMEM_TOT>>>(Y, L2);
}

// round 8
// speedup vs baseline: 1.9139x; 1.0307x over previous
#include <cuda_runtime.h>
#include <cuda_fp16.h>
#include <cstdint>

#define D_IN   4096
#define D_OUT  4096
#define NROWS  8192
#define RANK   16

// ---------------- scratch ----------------
__device__ __align__(1024) __half g_Wh[D_OUT * D_IN];  // W^T [N][K], fp16
__device__ __align__(1024) __half g_Xh[NROWS * D_IN];  // X, fp16
__device__ __align__(16)   float  g_T [NROWS * RANK];  // X @ L1 (fp32)

// ---------------- helpers ----------------
__device__ __forceinline__ uint32_t smem_u32(const void* p) {
    return (uint32_t)__cvta_generic_to_shared(p);
}
#define CP_ASYNC16(dst, src) \
    asm volatile("cp.async.cg.shared.global [%0], [%1], 16;\n" :: "r"(dst), "l"(src))
#define CP_COMMIT  asm volatile("cp.async.commit_group;\n" ::: "memory")
#define CP_WAIT2   asm volatile("cp.async.wait_group 2;\n" ::: "memory")

#define LDSM_X4(r0, r1, r2, r3, a) \
    asm volatile("ldmatrix.sync.aligned.m8n8.x4.shared.b16 {%0,%1,%2,%3}, [%4];" \
        : "=r"(r0), "=r"(r1), "=r"(r2), "=r"(r3) : "r"(a))

__device__ __forceinline__ void mma_16816(float* c, const uint32_t* a, const uint32_t* b) {
    asm volatile(
        "mma.sync.aligned.m16n8k16.row.col.f32.f16.f16.f32 "
        "{%0,%1,%2,%3}, {%4,%5,%6,%7}, {%8,%9}, {%0,%1,%2,%3};\n"
        : "+f"(c[0]), "+f"(c[1]), "+f"(c[2]), "+f"(c[3])
        : "r"(a[0]), "r"(a[1]), "r"(a[2]), "r"(a[3]), "r"(b[0]), "r"(b[1]));
}

// ============================================================
// Kernel 1: dequant + transpose to fp16: g_Wh[n][k] = h(W[k][n]*c1*ck[k][n])
// ============================================================
__global__ void dequant_t_kernel(const float* __restrict__ w,
                                 const float* __restrict__ c1p,
                                 const float* __restrict__ ck) {
    __shared__ float tile[32][33];
    const float c1 = c1p[0];
    const int n0 = blockIdx.x * 32, k0 = blockIdx.y * 32;
    const int tx = threadIdx.x, ty = threadIdx.y;   // (32, 8)
    #pragma unroll
    for (int i = 0; i < 4; i++) {
        int k = k0 + ty + i * 8;
        size_t idx = (size_t)k * D_OUT + n0 + tx;
        tile[ty + i * 8][tx] = (w[idx] * c1) * ck[idx];
    }
    __syncthreads();
    #pragma unroll
    for (int i = 0; i < 4; i++) {
        int n = n0 + ty + i * 8;
        g_Wh[(size_t)n * D_IN + k0 + tx] = __float2half_rn(tile[tx][ty + i * 8]);
    }
}

// ============================================================
// Kernel 2: fused  T = X @ L1  AND  g_Xh = fp16(X)
// ============================================================
__global__ void xl1_kernel(const float* __restrict__ X, const float* __restrict__ L1) {
    const int row0 = blockIdx.x * 2;
    const int tid  = threadIdx.x;
    const float4* x0 = (const float4*)(X + (size_t)row0 * D_IN);
    const float4* x1 = (const float4*)(X + (size_t)(row0 + 1) * D_IN);
    __half* xh0 = g_Xh + (size_t)row0 * D_IN;
    __half* xh1 = g_Xh + (size_t)(row0 + 1) * D_IN;

    float acc0[RANK], acc1[RANK];
    #pragma unroll
    for (int r = 0; r < RANK; r++) { acc0[r] = 0.f; acc1[r] = 0.f; }

    for (int k4 = tid; k4 < D_IN / 4; k4 += 128) {
        float4 xa = x0[k4];
        float4 xb = x1[k4];
        // fused fp16 conversion (replaces the old xconv pass over X)
        {
            __half2 p0 = __floats2half2_rn(xa.x, xa.y);
            __half2 p1 = __floats2half2_rn(xa.z, xa.w);
            uint2 u = make_uint2(*(uint32_t*)&p0, *(uint32_t*)&p1);
            *(uint2*)(xh0 + k4 * 4) = u;
            __half2 q0 = __floats2half2_rn(xb.x, xb.y);
            __half2 q1 = __floats2half2_rn(xb.z, xb.w);
            uint2 v = make_uint2(*(uint32_t*)&q0, *(uint32_t*)&q1);
            *(uint2*)(xh1 + k4 * 4) = v;
        }
        const float* l = L1 + k4 * 4 * RANK;
        #pragma unroll
        for (int r = 0; r < RANK; r++) {
            float l0 = l[r], l1 = l[RANK + r], l2 = l[2 * RANK + r], l3 = l[3 * RANK + r];
            acc0[r] += xa.x * l0 + xa.y * l1 + xa.z * l2 + xa.w * l3;
            acc1[r] += xb.x * l0 + xb.y * l1 + xb.z * l2 + xb.w * l3;
        }
    }
    #pragma unroll
    for (int off = 16; off > 0; off >>= 1) {
        #pragma unroll
        for (int r = 0; r < RANK; r++) {
            acc0[r] += __shfl_xor_sync(0xFFFFFFFF, acc0[r], off);
            acc1[r] += __shfl_xor_sync(0xFFFFFFFF, acc1[r], off);
        }
    }
    __shared__ float red[4][32];
    const int warp = tid >> 5, lane = tid & 31;
    if (lane == 0) {
        #pragma unroll
        for (int r = 0; r < RANK; r++) {
            red[warp][r]        = acc0[r];
            red[warp][RANK + r] = acc1[r];
        }
    }
    __syncthreads();
    if (tid < 32) {
        float s = red[0][tid] + red[1][tid] + red[2][tid] + red[3][tid];
        int r = tid & 15, which = tid >> 4;
        g_T[(size_t)(row0 + which) * RANK + r] = s;
    }
}

// ============================================================
// Kernel 3: fp16 mma.sync GEMM, BM=128 BN=256 BK=64, ldmatrix,
//           4-stage cp.async pipeline, ONE barrier/iter, fused LoRA
// ============================================================
#define BM 128
#define BN 256
#define BK 64                        // halfs; row = 128 B
#define KT (D_IN / BK)               // 64
#define A_BYTES (BM * BK * 2)        // 16384
#define B_BYTES (BN * BK * 2)        // 32768
#define STAGE_BYTES (A_BYTES + B_BYTES)
#define STAGES 4
#define SMEM_L2  (STAGES * STAGE_BYTES)      // 196608
#define SMEM_TS  (SMEM_L2 + RANK * BN * 4)   // +16384
#define SMEM_TOT (SMEM_TS + BM * RANK * 4)   // +8192 = 221184

__global__ __launch_bounds__(256, 1)
void gemm_hmma_kernel(float* __restrict__ Y, const float* __restrict__ L2) {
    extern __shared__ __align__(1024) unsigned char smem[];
    const uint32_t sbase = smem_u32(smem);
    const int tid = threadIdx.x, warp = tid >> 5, lane = tid & 31;
    const int bN = blockIdx.x, bM = blockIdx.y;
    const int wm = warp & 1, wn = warp >> 1;        // 2 x 4 warps, 64x64 tiles
    const int li = lane & 7, sel = lane >> 3;

    const __half* Ag = g_Xh + (size_t)(bM * BM) * D_IN;
    const __half* Bg = g_Wh + (size_t)(bN * BN) * D_IN;

    auto load_stage = [&](int buf, int kt) {
        const uint32_t ab = sbase + buf * STAGE_BYTES;
        const uint32_t bb = ab + A_BYTES;
        #pragma unroll
        for (int j = 0; j < 4; j++) {          // A: 128 rows x 8 chunks
            int id = tid + j * 256, r = id >> 3, c = id & 7;
            CP_ASYNC16(ab + r * 128 + (((c ^ (r & 7))) << 4),
                       Ag + (size_t)r * D_IN + kt * BK + c * 8);
        }
        #pragma unroll
        for (int j = 0; j < 8; j++) {          // B: 256 rows x 8 chunks
            int id = tid + j * 256, r = id >> 3, c = id & 7;
            CP_ASYNC16(bb + r * 128 + (((c ^ (r & 7))) << 4),
                       Bg + (size_t)r * D_IN + kt * BK + c * 8);
        }
        CP_COMMIT;
    };

    // prefetch 3 of 4 stages before anything else
    load_stage(0, 0);
    load_stage(1, 1);
    load_stage(2, 2);

    // LoRA operand tiles (plain LDG/STS, overlap with cp.async fills)
    float* l2s = (float*)(smem + SMEM_L2);     // [RANK][BN]
    float* ts  = (float*)(smem + SMEM_TS);     // [BM][RANK]
    #pragma unroll
    for (int j = 0; j < 4; j++) {              // 16*256 floats = 1024 float4
        int idx = tid + j * 256, r = idx >> 6, c4 = idx & 63;
        *(float4*)&l2s[r * BN + c4 * 4] =
            *(const float4*)&L2[(size_t)r * D_OUT + bN * BN + c4 * 4];
    }
    #pragma unroll
    for (int j = 0; j < 2; j++) {              // 128*16 floats = 512 float4
        int idx = tid + j * 256, r = idx >> 2, c4 = idx & 3;
        *(float4*)&ts[r * RANK + c4 * 4] =
            *(const float4*)&g_T[(size_t)(bM * BM + r) * RANK + c4 * 4];
    }

    float c[4][8][4];
    #pragma unroll
    for (int mt = 0; mt < 4; mt++)
        #pragma unroll
        for (int nt = 0; nt < 8; nt++)
            #pragma unroll
            for (int i = 0; i < 4; i++) c[mt][nt][i] = 0.f;

    const int a_selr = sel & 1, a_selc = sel >> 1;
    const int b_selr = sel >> 1, b_selc = sel & 1;

    for (int kt = 0; kt < KT; ++kt) {
        CP_WAIT2;                              // stage kt resident (3 groups out)
        __syncthreads();                       // single barrier per iteration
        if (kt + 3 < KT) load_stage((kt + 3) & 3, kt + 3);
        else             CP_COMMIT;            // empty group keeps count invariant

        const uint32_t ab = sbase + (kt & 3) * STAGE_BYTES;
        const uint32_t bb = ab + A_BYTES;

        #pragma unroll
        for (int ks = 0; ks < 4; ks++) {       // 4 x k16
            const int c0 = ks * 2;
            uint32_t a[4][4], b[8][2];
            #pragma unroll
            for (int mt = 0; mt < 4; mt++) {
                int row = wm * 64 + mt * 16 + li + a_selr * 8;
                int ch  = c0 + a_selc;
                LDSM_X4(a[mt][0], a[mt][1], a[mt][2], a[mt][3],
                        ab + row * 128 + (((ch ^ (row & 7))) << 4));
            }
            #pragma unroll
            for (int p = 0; p < 4; p++) {
                int row = wn * 64 + p * 16 + li + b_selr * 8;
                int ch  = c0 + b_selc;
                LDSM_X4(b[p * 2][0], b[p * 2][1], b[p * 2 + 1][0], b[p * 2 + 1][1],
                        bb + row * 128 + (((ch ^ (row & 7))) << 4));
            }
            #pragma unroll
            for (int mt = 0; mt < 4; mt++)
                #pragma unroll
                for (int nt = 0; nt < 8; nt++)
                    mma_16816(c[mt][nt], a[mt], b[nt]);
        }
        // no trailing barrier: next iteration's barrier orders buffer reuse
    }

    // ---------- epilogue: Y = C + T @ L2  (streaming stores keep X/W in L2) ----------
    const int r0 = lane >> 2, cp = (lane & 3) * 2;
    #pragma unroll
    for (int mt = 0; mt < 4; mt++) {
        const int lrA = wm * 64 + mt * 16 + r0;
        const int lrB = lrA + 8;
        float tA[RANK], tB[RANK];
        #pragma unroll
        for (int r = 0; r < RANK; r++) {
            tA[r] = ts[lrA * RANK + r];
            tB[r] = ts[lrB * RANK + r];
        }
        float* yA = Y + (size_t)(bM * BM + lrA) * D_OUT + bN * BN;
        float* yB = Y + (size_t)(bM * BM + lrB) * D_OUT + bN * BN;
        #pragma unroll
        for (int nt = 0; nt < 8; nt++) {
            const int col = wn * 64 + nt * 8 + cp;
            float2 aacc = make_float2(c[mt][nt][0], c[mt][nt][1]);
            float2 bacc = make_float2(c[mt][nt][2], c[mt][nt][3]);
            #pragma unroll
            for (int r = 0; r < RANK; r++) {
                float2 l = *(const float2*)&l2s[r * BN + col];
                aacc.x += tA[r] * l.x; aacc.y += tA[r] * l.y;
                bacc.x += tB[r] * l.x; bacc.y += tB[r] * l.y;
            }
            __stcs((float2*)(yA + col), aacc);
            __stcs((float2*)(yB + col), bacc);
        }
    }
}

// ============================================================
// launch
// ============================================================
extern "C" void kernel_launch(void* const* d_in, const int* in_sizes, int n_in,
                              void* d_out, int out_size) {
    const float* X  = (const float*)d_in[0];
    const float* Wn = (const float*)d_in[1];
    const float* c1 = (const float*)d_in[2];
    const float* ck = (const float*)d_in[3];
    const float* L1 = (const float*)d_in[4];
    const float* L2 = (const float*)d_in[5];
    float* Y = (float*)d_out;

    cudaFuncSetAttribute(gemm_hmma_kernel,
                         cudaFuncAttributeMaxDynamicSharedMemorySize, SMEM_TOT);

    dequant_t_kernel<<<dim3(D_OUT / 32, D_IN / 32), dim3(32, 8)>>>(Wn, c1, ck);
    xl1_kernel<<<NROWS / 2, 128>>>(X, L1);
    gemm_hmma_kernel<<<dim3(D_OUT / BN, NROWS / BM), 256, SMEM_TOT>>>(Y, L2);
}

// round 9
// speedup vs baseline: 3.6793x; 1.9224x over previous
#include <cuda_runtime.h>
#include <cuda_fp16.h>
#include <cstdint>

#define D_IN   4096
#define D_OUT  4096
#define NROWS  8192
#define RANK   16

// ---------------- scratch ----------------
__device__ __align__(1024) __half g_Wh[D_OUT * D_IN];  // W^T [N][K], fp16
__device__ __align__(1024) __half g_Xh[NROWS * D_IN];  // X, fp16
__device__ __align__(16)   float  g_T [NROWS * RANK];  // X @ L1 (fp32)
#define KSPLIT 8
__device__ __align__(16)   float  g_Tp[KSPLIT * NROWS * RANK]; // partials

// ---------------- helpers ----------------
__device__ __forceinline__ uint32_t smem_u32(const void* p) {
    return (uint32_t)__cvta_generic_to_shared(p);
}
#define CP_ASYNC16(dst, src) \
    asm volatile("cp.async.cg.shared.global [%0], [%1], 16;\n" :: "r"(dst), "l"(src))
#define CP_COMMIT  asm volatile("cp.async.commit_group;\n" ::: "memory")
#define CP_WAIT2   asm volatile("cp.async.wait_group 2;\n" ::: "memory")

#define LDSM_X4(r0, r1, r2, r3, a) \
    asm volatile("ldmatrix.sync.aligned.m8n8.x4.shared.b16 {%0,%1,%2,%3}, [%4];" \
        : "=r"(r0), "=r"(r1), "=r"(r2), "=r"(r3) : "r"(a))

__device__ __forceinline__ void mma_16816(float* c, const uint32_t* a, const uint32_t* b) {
    asm volatile(
        "mma.sync.aligned.m16n8k16.row.col.f32.f16.f16.f32 "
        "{%0,%1,%2,%3}, {%4,%5,%6,%7}, {%8,%9}, {%0,%1,%2,%3};\n"
        : "+f"(c[0]), "+f"(c[1]), "+f"(c[2]), "+f"(c[3])
        : "r"(a[0]), "r"(a[1]), "r"(a[2]), "r"(a[3]), "r"(b[0]), "r"(b[1]));
}

// ============================================================
// Kernel 1: dequant + transpose to fp16: g_Wh[n][k] = h(W[k][n]*c1*ck[k][n])
// ============================================================
__global__ void dequant_t_kernel(const float* __restrict__ w,
                                 const float* __restrict__ c1p,
                                 const float* __restrict__ ck) {
    __shared__ float tile[32][33];
    const float c1 = c1p[0];
    const int n0 = blockIdx.x * 32, k0 = blockIdx.y * 32;
    const int tx = threadIdx.x, ty = threadIdx.y;   // (32, 8)
    #pragma unroll
    for (int i = 0; i < 4; i++) {
        int k = k0 + ty + i * 8;
        size_t idx = (size_t)k * D_OUT + n0 + tx;
        tile[ty + i * 8][tx] = (w[idx] * c1) * ck[idx];
    }
    __syncthreads();
    #pragma unroll
    for (int i = 0; i < 4; i++) {
        int n = n0 + ty + i * 8;
        g_Wh[(size_t)n * D_IN + k0 + tx] = __float2half_rn(tile[tx][ty + i * 8]);
    }
}

// ============================================================
// Kernel 2: retiled T-partial = X @ L1 (+ fused fp16(X) conversion)
// grid (KSPLIT, NROWS/256), block 256; thread = row; L1 tile in smem.
// ============================================================
#define KCHUNK (D_IN / KSPLIT)   // 512
#define XTK 32                   // k per tile
#define XROWS 256

__global__ __launch_bounds__(256)
void xl1_kernel(const float* __restrict__ X, const float* __restrict__ L1) {
    __shared__ float xs[XROWS * 33];                  // stride 33: conflict-free
    __shared__ __align__(16) float l1s[XTK][RANK];
    const int tid  = threadIdx.x;
    const int ks   = blockIdx.x;
    const int row0 = blockIdx.y * XROWS;
    const int k0   = ks * KCHUNK;

    float acc[RANK];
    #pragma unroll
    for (int r = 0; r < RANK; r++) acc[r] = 0.f;

    for (int t = 0; t < KCHUNK / XTK; t++) {          // 16 tiles
        const int kt = k0 + t * XTK;
        __syncthreads();                               // xs/l1s reuse guard
        // stage X[256][32] (+ fp16 conversion, same data)
        #pragma unroll
        for (int j = 0; j < 8; j++) {
            int f = tid + j * 256;                     // float4 id
            int row = f >> 3, seg = f & 7;
            float4 v = *(const float4*)(X + (size_t)(row0 + row) * D_IN + kt + seg * 4);
            float* xd = xs + row * 33 + seg * 4;
            xd[0] = v.x; xd[1] = v.y; xd[2] = v.z; xd[3] = v.w;
            __half2 h0 = __floats2half2_rn(v.x, v.y);
            __half2 h1 = __floats2half2_rn(v.z, v.w);
            uint2 u = make_uint2(*(uint32_t*)&h0, *(uint32_t*)&h1);
            *(uint2*)(g_Xh + (size_t)(row0 + row) * D_IN + kt + seg * 4) = u;
        }
        // stage L1[32][16]
        if (tid < 128) {
            int kk = tid >> 2, rq = tid & 3;
            *(float4*)&l1s[kk][rq * 4] =
                *(const float4*)(L1 + (size_t)(kt + kk) * RANK + rq * 4);
        }
        __syncthreads();
        // compute: one row per thread, L1 via broadcast LDS
        const float* xr = xs + tid * 33;
        #pragma unroll
        for (int kk = 0; kk < XTK; kk++) {
            float x = xr[kk];
            float4 a = *(const float4*)&l1s[kk][0];
            float4 b = *(const float4*)&l1s[kk][4];
            float4 c = *(const float4*)&l1s[kk][8];
            float4 d = *(const float4*)&l1s[kk][12];
            acc[0]  += x * a.x; acc[1]  += x * a.y; acc[2]  += x * a.z; acc[3]  += x * a.w;
            acc[4]  += x * b.x; acc[5]  += x * b.y; acc[6]  += x * b.z; acc[7]  += x * b.w;
            acc[8]  += x * c.x; acc[9]  += x * c.y; acc[10] += x * c.z; acc[11] += x * c.w;
            acc[12] += x * d.x; acc[13] += x * d.y; acc[14] += x * d.z; acc[15] += x * d.w;
        }
    }
    float* out = g_Tp + ((size_t)ks * NROWS + row0 + tid) * RANK;
    #pragma unroll
    for (int q = 0; q < 4; q++)
        *(float4*)(out + q * 4) = make_float4(acc[q * 4], acc[q * 4 + 1],
                                              acc[q * 4 + 2], acc[q * 4 + 3]);
}

// ============================================================
// Kernel 2b: g_T = sum over k-split partials
// ============================================================
__global__ void treduce_kernel() {
    const int i = (blockIdx.x * 256 + threadIdx.x) * 4;
    float4 s = make_float4(0.f, 0.f, 0.f, 0.f);
    #pragma unroll
    for (int ks = 0; ks < KSPLIT; ks++) {
        float4 v = *(const float4*)(g_Tp + (size_t)ks * NROWS * RANK + i);
        s.x += v.x; s.y += v.y; s.z += v.z; s.w += v.w;
    }
    *(float4*)(g_T + i) = s;
}

// ============================================================
// Kernel 3: fp16 mma.sync GEMM, BM=128 BN=256 BK=64, ldmatrix,
//           4-stage cp.async pipeline, ONE barrier/iter, fused LoRA
// ============================================================
#define BM 128
#define BN 256
#define BK 64                        // halfs; row = 128 B
#define KT (D_IN / BK)               // 64
#define A_BYTES (BM * BK * 2)        // 16384
#define B_BYTES (BN * BK * 2)        // 32768
#define STAGE_BYTES (A_BYTES + B_BYTES)
#define STAGES 4
#define SMEM_L2  (STAGES * STAGE_BYTES)      // 196608
#define SMEM_TS  (SMEM_L2 + RANK * BN * 4)   // +16384
#define SMEM_TOT (SMEM_TS + BM * RANK * 4)   // +8192 = 221184

__global__ __launch_bounds__(256, 1)
void gemm_hmma_kernel(float* __restrict__ Y, const float* __restrict__ L2) {
    extern __shared__ __align__(1024) unsigned char smem[];
    const uint32_t sbase = smem_u32(smem);
    const int tid = threadIdx.x, warp = tid >> 5, lane = tid & 31;
    const int bN = blockIdx.x, bM = blockIdx.y;
    const int wm = warp & 1, wn = warp >> 1;        // 2 x 4 warps, 64x64 tiles
    const int li = lane & 7, sel = lane >> 3;

    const __half* Ag = g_Xh + (size_t)(bM * BM) * D_IN;
    const __half* Bg = g_Wh + (size_t)(bN * BN) * D_IN;

    auto load_stage = [&](int buf, int kt) {
        const uint32_t ab = sbase + buf * STAGE_BYTES;
        const uint32_t bb = ab + A_BYTES;
        #pragma unroll
        for (int j = 0; j < 4; j++) {          // A: 128 rows x 8 chunks
            int id = tid + j * 256, r = id >> 3, c = id & 7;
            CP_ASYNC16(ab + r * 128 + (((c ^ (r & 7))) << 4),
                       Ag + (size_t)r * D_IN + kt * BK + c * 8);
        }
        #pragma unroll
        for (int j = 0; j < 8; j++) {          // B: 256 rows x 8 chunks
            int id = tid + j * 256, r = id >> 3, c = id & 7;
            CP_ASYNC16(bb + r * 128 + (((c ^ (r & 7))) << 4),
                       Bg + (size_t)r * D_IN + kt * BK + c * 8);
        }
        CP_COMMIT;
    };

    load_stage(0, 0);
    load_stage(1, 1);
    load_stage(2, 2);

    float* l2s = (float*)(smem + SMEM_L2);     // [RANK][BN]
    float* ts  = (float*)(smem + SMEM_TS);     // [BM][RANK]
    #pragma unroll
    for (int j = 0; j < 4; j++) {
        int idx = tid + j * 256, r = idx >> 6, c4 = idx & 63;
        *(float4*)&l2s[r * BN + c4 * 4] =
            *(const float4*)&L2[(size_t)r * D_OUT + bN * BN + c4 * 4];
    }
    #pragma unroll
    for (int j = 0; j < 2; j++) {
        int idx = tid + j * 256, r = idx >> 2, c4 = idx & 3;
        *(float4*)&ts[r * RANK + c4 * 4] =
            *(const float4*)&g_T[(size_t)(bM * BM + r) * RANK + c4 * 4];
    }

    float c[4][8][4];
    #pragma unroll
    for (int mt = 0; mt < 4; mt++)
        #pragma unroll
        for (int nt = 0; nt < 8; nt++)
            #pragma unroll
            for (int i = 0; i < 4; i++) c[mt][nt][i] = 0.f;

    const int a_selr = sel & 1, a_selc = sel >> 1;
    const int b_selr = sel >> 1, b_selc = sel & 1;

    for (int kt = 0; kt < KT; ++kt) {
        CP_WAIT2;
        __syncthreads();
        if (kt + 3 < KT) load_stage((kt + 3) & 3, kt + 3);
        else             CP_COMMIT;

        const uint32_t ab = sbase + (kt & 3) * STAGE_BYTES;
        const uint32_t bb = ab + A_BYTES;

        #pragma unroll
        for (int ks = 0; ks < 4; ks++) {
            const int c0 = ks * 2;
            uint32_t a[4][4], b[8][2];
            #pragma unroll
            for (int mt = 0; mt < 4; mt++) {
                int row = wm * 64 + mt * 16 + li + a_selr * 8;
                int ch  = c0 + a_selc;
                LDSM_X4(a[mt][0], a[mt][1], a[mt][2], a[mt][3],
                        ab + row * 128 + (((ch ^ (row & 7))) << 4));
            }
            #pragma unroll
            for (int p = 0; p < 4; p++) {
                int row = wn * 64 + p * 16 + li + b_selr * 8;
                int ch  = c0 + b_selc;
                LDSM_X4(b[p * 2][0], b[p * 2][1], b[p * 2 + 1][0], b[p * 2 + 1][1],
                        bb + row * 128 + (((ch ^ (row & 7))) << 4));
            }
            #pragma unroll
            for (int mt = 0; mt < 4; mt++)
                #pragma unroll
                for (int nt = 0; nt < 8; nt++)
                    mma_16816(c[mt][nt], a[mt], b[nt]);
        }
    }

    // ---------- epilogue: Y = C + T @ L2 ----------
    const int r0 = lane >> 2, cp = (lane & 3) * 2;
    #pragma unroll
    for (int mt = 0; mt < 4; mt++) {
        const int lrA = wm * 64 + mt * 16 + r0;
        const int lrB = lrA + 8;
        float tA[RANK], tB[RANK];
        #pragma unroll
        for (int r = 0; r < RANK; r++) {
            tA[r] = ts[lrA * RANK + r];
            tB[r] = ts[lrB * RANK + r];
        }
        float* yA = Y + (size_t)(bM * BM + lrA) * D_OUT + bN * BN;
        float* yB = Y + (size_t)(bM * BM + lrB) * D_OUT + bN * BN;
        #pragma unroll
        for (int nt = 0; nt < 8; nt++) {
            const int col = wn * 64 + nt * 8 + cp;
            float2 aacc = make_float2(c[mt][nt][0], c[mt][nt][1]);
            float2 bacc = make_float2(c[mt][nt][2], c[mt][nt][3]);
            #pragma unroll
            for (int r = 0; r < RANK; r++) {
                float2 l = *(const float2*)&l2s[r * BN + col];
                aacc.x += tA[r] * l.x; aacc.y += tA[r] * l.y;
                bacc.x += tB[r] * l.x; bacc.y += tB[r] * l.y;
            }
            __stcs((float2*)(yA + col), aacc);
            __stcs((float2*)(yB + col), bacc);
        }
    }
}

// ============================================================
// launch
// ============================================================
extern "C" void kernel_launch(void* const* d_in, const int* in_sizes, int n_in,
                              void* d_out, int out_size) {
    const float* X  = (const float*)d_in[0];
    const float* Wn = (const float*)d_in[1];
    const float* c1 = (const float*)d_in[2];
    const float* ck = (const float*)d_in[3];
    const float* L1 = (const float*)d_in[4];
    const float* L2 = (const float*)d_in[5];
    float* Y = (float*)d_out;

    cudaFuncSetAttribute(gemm_hmma_kernel,
                         cudaFuncAttributeMaxDynamicSharedMemorySize, SMEM_TOT);

    dequant_t_kernel<<<dim3(D_OUT / 32, D_IN / 32), dim3(32, 8)>>>(Wn, c1, ck);
    xl1_kernel<<<dim3(KSPLIT, NROWS / XROWS), 256>>>(X, L1);
    treduce_kernel<<<(NROWS * RANK / 4) / 256, 256>>>();
    gemm_hmma_kernel<<<dim3(D_OUT / BN, NROWS / BM), 256, SMEM_TOT>>>(Y, L2);
}

// round 10
// speedup vs baseline: 3.7166x; 1.0101x over previous
#include <cuda_runtime.h>
#include <cuda_fp16.h>
#include <cstdint>

#define D_IN   4096
#define D_OUT  4096
#define NROWS  8192
#define RANK   16

// ---------------- scratch ----------------
__device__ __align__(1024) __half g_Wh[D_OUT * D_IN];  // W^T [N][K], fp16
__device__ __align__(1024) __half g_Xh[NROWS * D_IN];  // X, fp16
__device__ __align__(16)   float  g_T [NROWS * RANK];  // X @ L1 (fp32)
#define KSPLIT 8
__device__ __align__(16)   float  g_Tp[KSPLIT * NROWS * RANK]; // partials

// ---------------- helpers ----------------
__device__ __forceinline__ uint32_t smem_u32(const void* p) {
    return (uint32_t)__cvta_generic_to_shared(p);
}
#define CP_ASYNC16(dst, src) \
    asm volatile("cp.async.cg.shared.global [%0], [%1], 16;\n" :: "r"(dst), "l"(src))
#define CP_COMMIT  asm volatile("cp.async.commit_group;\n" ::: "memory")
#define CP_WAIT2   asm volatile("cp.async.wait_group 2;\n" ::: "memory")

#define LDSM_X4(r0, r1, r2, r3, a) \
    asm volatile("ldmatrix.sync.aligned.m8n8.x4.shared.b16 {%0,%1,%2,%3}, [%4];" \
        : "=r"(r0), "=r"(r1), "=r"(r2), "=r"(r3) : "r"(a))

__device__ __forceinline__ void mma_16816(float* c, const uint32_t* a, const uint32_t* b) {
    asm volatile(
        "mma.sync.aligned.m16n8k16.row.col.f32.f16.f16.f32 "
        "{%0,%1,%2,%3}, {%4,%5,%6,%7}, {%8,%9}, {%0,%1,%2,%3};\n"
        : "+f"(c[0]), "+f"(c[1]), "+f"(c[2]), "+f"(c[3])
        : "r"(a[0]), "r"(a[1]), "r"(a[2]), "r"(a[3]), "r"(b[0]), "r"(b[1]));
}

// ============================================================
// Kernel 1: dequant + transpose to fp16: g_Wh[n][k] = h(W[k][n]*c1*ck[k][n])
// ============================================================
__global__ void dequant_t_kernel(const float* __restrict__ w,
                                 const float* __restrict__ c1p,
                                 const float* __restrict__ ck) {
    __shared__ float tile[32][33];
    const float c1 = c1p[0];
    const int n0 = blockIdx.x * 32, k0 = blockIdx.y * 32;
    const int tx = threadIdx.x, ty = threadIdx.y;   // (32, 8)
    #pragma unroll
    for (int i = 0; i < 4; i++) {
        int k = k0 + ty + i * 8;
        size_t idx = (size_t)k * D_OUT + n0 + tx;
        tile[ty + i * 8][tx] = (w[idx] * c1) * ck[idx];
    }
    __syncthreads();
    #pragma unroll
    for (int i = 0; i < 4; i++) {
        int n = n0 + ty + i * 8;
        g_Wh[(size_t)n * D_IN + k0 + tx] = __float2half_rn(tile[tx][ty + i * 8]);
    }
}

// ============================================================
// Kernel 2: retiled T-partial = X @ L1 (+ fused fp16(X) conversion)
// ============================================================
#define KCHUNK (D_IN / KSPLIT)   // 512
#define XTK 32
#define XROWS 256

__global__ __launch_bounds__(256)
void xl1_kernel(const float* __restrict__ X, const float* __restrict__ L1) {
    __shared__ float xs[XROWS * 33];
    __shared__ __align__(16) float l1s[XTK][RANK];
    const int tid  = threadIdx.x;
    const int ks   = blockIdx.x;
    const int row0 = blockIdx.y * XROWS;
    const int k0   = ks * KCHUNK;

    float acc[RANK];
    #pragma unroll
    for (int r = 0; r < RANK; r++) acc[r] = 0.f;

    for (int t = 0; t < KCHUNK / XTK; t++) {
        const int kt = k0 + t * XTK;
        __syncthreads();
        #pragma unroll
        for (int j = 0; j < 8; j++) {
            int f = tid + j * 256;
            int row = f >> 3, seg = f & 7;
            float4 v = *(const float4*)(X + (size_t)(row0 + row) * D_IN + kt + seg * 4);
            float* xd = xs + row * 33 + seg * 4;
            xd[0] = v.x; xd[1] = v.y; xd[2] = v.z; xd[3] = v.w;
            __half2 h0 = __floats2half2_rn(v.x, v.y);
            __half2 h1 = __floats2half2_rn(v.z, v.w);
            uint2 u = make_uint2(*(uint32_t*)&h0, *(uint32_t*)&h1);
            *(uint2*)(g_Xh + (size_t)(row0 + row) * D_IN + kt + seg * 4) = u;
        }
        if (tid < 128) {
            int kk = tid >> 2, rq = tid & 3;
            *(float4*)&l1s[kk][rq * 4] =
                *(const float4*)(L1 + (size_t)(kt + kk) * RANK + rq * 4);
        }
        __syncthreads();
        const float* xr = xs + tid * 33;
        #pragma unroll
        for (int kk = 0; kk < XTK; kk++) {
            float x = xr[kk];
            float4 a = *(const float4*)&l1s[kk][0];
            float4 b = *(const float4*)&l1s[kk][4];
            float4 c = *(const float4*)&l1s[kk][8];
            float4 d = *(const float4*)&l1s[kk][12];
            acc[0]  += x * a.x; acc[1]  += x * a.y; acc[2]  += x * a.z; acc[3]  += x * a.w;
            acc[4]  += x * b.x; acc[5]  += x * b.y; acc[6]  += x * b.z; acc[7]  += x * b.w;
            acc[8]  += x * c.x; acc[9]  += x * c.y; acc[10] += x * c.z; acc[11] += x * c.w;
            acc[12] += x * d.x; acc[13] += x * d.y; acc[14] += x * d.z; acc[15] += x * d.w;
        }
    }
    float* out = g_Tp + ((size_t)ks * NROWS + row0 + tid) * RANK;
    #pragma unroll
    for (int q = 0; q < 4; q++)
        *(float4*)(out + q * 4) = make_float4(acc[q * 4], acc[q * 4 + 1],
                                              acc[q * 4 + 2], acc[q * 4 + 3]);
}

// ============================================================
// Kernel 2b: g_T = sum over k-split partials
// ============================================================
__global__ void treduce_kernel() {
    const int i = (blockIdx.x * 256 + threadIdx.x) * 4;
    float4 s = make_float4(0.f, 0.f, 0.f, 0.f);
    #pragma unroll
    for (int ks = 0; ks < KSPLIT; ks++) {
        float4 v = *(const float4*)(g_Tp + (size_t)ks * NROWS * RANK + i);
        s.x += v.x; s.y += v.y; s.z += v.z; s.w += v.w;
    }
    *(float4*)(g_T + i) = s;
}

// ============================================================
// Kernel 3: fp16 mma.sync GEMM + double-buffered LDSM fragments
// ============================================================
#define BM 128
#define BN 256
#define BK 64
#define KTILES (D_IN / BK)           // 64
#define A_BYTES (BM * BK * 2)        // 16384
#define B_BYTES (BN * BK * 2)        // 32768
#define STAGE_BYTES (A_BYTES + B_BYTES)
#define STAGES 4
#define SMEM_L2  (STAGES * STAGE_BYTES)
#define SMEM_TS  (SMEM_L2 + RANK * BN * 4)
#define SMEM_TOT (SMEM_TS + BM * RANK * 4)   // 221184

__global__ __launch_bounds__(256, 1)
void gemm_hmma_kernel(float* __restrict__ Y, const float* __restrict__ L2) {
    extern __shared__ __align__(1024) unsigned char smem[];
    const uint32_t sbase = smem_u32(smem);
    const int tid = threadIdx.x, warp = tid >> 5, lane = tid & 31;
    const int bN = blockIdx.x, bM = blockIdx.y;
    const int wm = warp & 1, wn = warp >> 1;
    const int li = lane & 7, sel = lane >> 3;

    const __half* Ag = g_Xh + (size_t)(bM * BM) * D_IN;
    const __half* Bg = g_Wh + (size_t)(bN * BN) * D_IN;

    auto load_stage = [&](int buf, int kt) {
        const uint32_t ab = sbase + buf * STAGE_BYTES;
        const uint32_t bb = ab + A_BYTES;
        #pragma unroll
        for (int j = 0; j < 4; j++) {
            int id = tid + j * 256, r = id >> 3, c = id & 7;
            CP_ASYNC16(ab + r * 128 + (((c ^ (r & 7))) << 4),
                       Ag + (size_t)r * D_IN + kt * BK + c * 8);
        }
        #pragma unroll
        for (int j = 0; j < 8; j++) {
            int id = tid + j * 256, r = id >> 3, c = id & 7;
            CP_ASYNC16(bb + r * 128 + (((c ^ (r & 7))) << 4),
                       Bg + (size_t)r * D_IN + kt * BK + c * 8);
        }
        CP_COMMIT;
    };

    load_stage(0, 0);
    load_stage(1, 1);
    load_stage(2, 2);

    float* l2s = (float*)(smem + SMEM_L2);
    float* ts  = (float*)(smem + SMEM_TS);
    #pragma unroll
    for (int j = 0; j < 4; j++) {
        int idx = tid + j * 256, r = idx >> 6, c4 = idx & 63;
        *(float4*)&l2s[r * BN + c4 * 4] =
            *(const float4*)&L2[(size_t)r * D_OUT + bN * BN + c4 * 4];
    }
    #pragma unroll
    for (int j = 0; j < 2; j++) {
        int idx = tid + j * 256, r = idx >> 2, c4 = idx & 3;
        *(float4*)&ts[r * RANK + c4 * 4] =
            *(const float4*)&g_T[(size_t)(bM * BM + r) * RANK + c4 * 4];
    }

    float c[4][8][4];
    #pragma unroll
    for (int mt = 0; mt < 4; mt++)
        #pragma unroll
        for (int nt = 0; nt < 8; nt++)
            #pragma unroll
            for (int i = 0; i < 4; i++) c[mt][nt][i] = 0.f;

    const int a_selr = sel & 1, a_selc = sel >> 1;
    const int b_selr = sel >> 1, b_selc = sel & 1;

    // double-buffered register fragments
    uint32_t a[2][4][4], b[2][8][2];

    auto load_frags = [&](int fb, uint32_t ab, uint32_t bb, int ks) {
        const int c0 = ks * 2;
        #pragma unroll
        for (int mt = 0; mt < 4; mt++) {
            int row = wm * 64 + mt * 16 + li + a_selr * 8;
            int ch  = c0 + a_selc;
            LDSM_X4(a[fb][mt][0], a[fb][mt][1], a[fb][mt][2], a[fb][mt][3],
                    ab + row * 128 + (((ch ^ (row & 7))) << 4));
        }
        #pragma unroll
        for (int p = 0; p < 4; p++) {
            int row = wn * 64 + p * 16 + li + b_selr * 8;
            int ch  = c0 + b_selc;
            LDSM_X4(b[fb][p * 2][0], b[fb][p * 2][1], b[fb][p * 2 + 1][0], b[fb][p * 2 + 1][1],
                    bb + row * 128 + (((ch ^ (row & 7))) << 4));
        }
    };

    for (int kt = 0; kt < KTILES; ++kt) {
        CP_WAIT2;
        __syncthreads();

        const uint32_t ab = sbase + (kt & 3) * STAGE_BYTES;
        const uint32_t bb = ab + A_BYTES;

        load_frags(0, ab, bb, 0);              // LDSM starts immediately post-barrier
        if (kt + 3 < KTILES) load_stage((kt + 3) & 3, kt + 3);
        else                 CP_COMMIT;

        #pragma unroll
        for (int ks = 0; ks < 4; ks++) {
            if (ks < 3) load_frags((ks + 1) & 1, ab, bb, ks + 1);  // hide LDSM under HMMA
            const int fb = ks & 1;
            #pragma unroll
            for (int mt = 0; mt < 4; mt++)
                #pragma unroll
                for (int nt = 0; nt < 8; nt++)
                    mma_16816(c[mt][nt], a[fb][mt], b[fb][nt]);
        }
    }

    // ---------- epilogue: Y = C + T @ L2 ----------
    const int r0 = lane >> 2, cp = (lane & 3) * 2;
    #pragma unroll
    for (int mt = 0; mt < 4; mt++) {
        const int lrA = wm * 64 + mt * 16 + r0;
        const int lrB = lrA + 8;
        float tA[RANK], tB[RANK];
        #pragma unroll
        for (int r = 0; r < RANK; r++) {
            tA[r] = ts[lrA * RANK + r];
            tB[r] = ts[lrB * RANK + r];
        }
        float* yA = Y + (size_t)(bM * BM + lrA) * D_OUT + bN * BN;
        float* yB = Y + (size_t)(bM * BM + lrB) * D_OUT + bN * BN;
        #pragma unroll
        for (int nt = 0; nt < 8; nt++) {
            const int col = wn * 64 + nt * 8 + cp;
            float2 aacc = make_float2(c[mt][nt][0], c[mt][nt][1]);
            float2 bacc = make_float2(c[mt][nt][2], c[mt][nt][3]);
            #pragma unroll
            for (int r = 0; r < RANK; r++) {
                float2 l = *(const float2*)&l2s[r * BN + col];
                aacc.x += tA[r] * l.x; aacc.y += tA[r] * l.y;
                bacc.x += tB[r] * l.x; bacc.y += tB[r] * l.y;
            }
            __stcs((float2*)(yA + col), aacc);
            __stcs((float2*)(yB + col), bacc);
        }
    }
}

// ============================================================
// launch
// ============================================================
extern "C" void kernel_launch(void* const* d_in, const int* in_sizes, int n_in,
                              void* d_out, int out_size) {
    const float* X  = (const float*)d_in[0];
    const float* Wn = (const float*)d_in[1];
    const float* c1 = (const float*)d_in[2];
    const float* ck = (const float*)d_in[3];
    const float* L1 = (const float*)d_in[4];
    const float* L2 = (const float*)d_in[5];
    float* Y = (float*)d_out;

    cudaFuncSetAttribute(gemm_hmma_kernel,
                         cudaFuncAttributeMaxDynamicSharedMemorySize, SMEM_TOT);

    dequant_t_kernel<<<dim3(D_OUT / 32, D_IN / 32), dim3(32, 8)>>>(Wn, c1, ck);
    xl1_kernel<<<dim3(KSPLIT, NROWS / XROWS), 256>>>(X, L1);
    treduce_kernel<<<(NROWS * RANK / 4) / 256, 256>>>();
    gemm_hmma_kernel<<<dim3(D_OUT / BN, NROWS / BM), 256, SMEM_TOT>>>(Y, L2);
}